// round 13
// baseline (speedup 1.0000x reference)
#include <cuda_runtime.h>
#include <cuda_bf16.h>
#include <cstdint>

#define F_DIM 128
#define H_DIM 64
#define TILE_E 128
#define THREADS 128

// ---- dynamic smem byte offsets ----
#define SM_B_HI 0            // 128 k-rows x 128 B (bf16 W hi), XOR-swizzled
#define SM_B_LO 16384
#define SM_B1   32768        // 64 f
#define SM_W2   33024        // 64 f
#define SM_FMS  33280        // 128 f
#define SM_ACC  33792        // 8 f
#define SM_TOTAL 33856

__device__ __forceinline__ uint32_t smem_u32(const void* p) {
    uint32_t a;
    asm("{ .reg .u64 t; cvta.to.shared.u64 t, %1; cvt.u32.u64 %0, t; }" : "=r"(a) : "l"(p));
    return a;
}
__device__ __forceinline__ uint32_t pack_bf16x2(float lo, float hi) {
    uint32_t r;
    asm("cvt.rn.bf16x2.f32 %0, %1, %2;" : "=r"(r) : "f"(hi), "f"(lo));
    return r;
}
// split one float2 into packed bf16x2 hi and lo parts
__device__ __forceinline__ void cvt_split(float2 v, uint32_t& h, uint32_t& l) {
    __nv_bfloat16 hx = __float2bfloat16_rn(v.x);
    __nv_bfloat16 hy = __float2bfloat16_rn(v.y);
    float fhx = __bfloat162float(hx);
    float fhy = __bfloat162float(hy);
    h = pack_bf16x2(fhx, fhy);
    l = pack_bf16x2(v.x - fhx, v.y - fhy);
}
__device__ __forceinline__ void ldmx4t(uint32_t addr, uint32_t* r) {
    asm volatile("ldmatrix.sync.aligned.m8n8.x4.trans.shared.b16 {%0,%1,%2,%3}, [%4];"
                 : "=r"(r[0]), "=r"(r[1]), "=r"(r[2]), "=r"(r[3]) : "r"(addr));
}
__device__ __forceinline__ void mma16816(float* c, const uint32_t* a, const uint32_t* b) {
    asm volatile(
        "mma.sync.aligned.m16n8k16.row.col.f32.bf16.bf16.f32 "
        "{%0,%1,%2,%3}, {%4,%5,%6,%7}, {%8,%9}, {%0,%1,%2,%3};"
        : "+f"(c[0]), "+f"(c[1]), "+f"(c[2]), "+f"(c[3])
        : "r"(a[0]), "r"(a[1]), "r"(a[2]), "r"(a[3]), "r"(b[0]), "r"(b[1]));
}
// shifted softplus: softplus(x) - ln(2)
__device__ __forceinline__ float ssp(float x) {
    float ax = fabsf(x);
    float l = __logf(1.0f + __expf(-ax));
    return fmaxf(x, 0.0f) + l - 0.69314718055994530942f;
}

__global__ __launch_bounds__(THREADS, 3)
void force_mapping_kernel(const float* __restrict__ X,
                          const float* __restrict__ U,
                          const float* __restrict__ W1,
                          const float* __restrict__ B1,
                          const float* __restrict__ W2,
                          const float* __restrict__ B2,
                          float* __restrict__ out)
{
    extern __shared__ char smem[];
    const uint32_t sbase = smem_u32(smem);
    const int tid = threadIdx.x;
    const int wid = tid >> 5;
    const int L   = tid & 31;
    const int g   = blockIdx.x;
    const int m0  = wid * 32;

    float* b1s  = reinterpret_cast<float*>(smem + SM_B1);
    float* W2s  = reinterpret_cast<float*>(smem + SM_W2);
    float* fms  = reinterpret_cast<float*>(smem + SM_FMS);
    float* acc6 = reinterpret_cast<float*>(smem + SM_ACC);

    if (tid < 8) acc6[tid] = 0.0f;

    // ---- A fragment base pointer: row = m0 + L/4, col = (L%4)*2 ----
    const float* xp = X + ((size_t)g * TILE_E + m0 + (L >> 2)) * F_DIM + (L & 3) * 2;

    // pf[buf][j]: j = row{0,8,16,24} x col{+0,+8}, interleaved (r0c0,r0c8,r1c0,...)
    float2 pf[2][8];
    #pragma unroll
    for (int rr = 0; rr < 4; ++rr) {
        const float* rp = xp + rr * 8 * F_DIM;
        pf[0][rr * 2 + 0] = *reinterpret_cast<const float2*>(rp);
        pf[0][rr * 2 + 1] = *reinterpret_cast<const float2*>(rp + 8);
        pf[1][rr * 2 + 0] = *reinterpret_cast<const float2*>(rp + 16);
        pf[1][rr * 2 + 1] = *reinterpret_cast<const float2*>(rp + 24);
    }

    // ---- convert W1 (K=128 rows x N=64, row-major) -> bf16 hi/lo smem, swizzled ----
    {
        #pragma unroll
        for (int it = 0; it < 8; ++it) {
            int q  = tid + THREADS * it;         // 0..1023
            int k  = q >> 3;                     // 0..127
            int c  = q & 7;                      // n chunk (8 floats)
            const float4* gw = reinterpret_cast<const float4*>(W1 + k * H_DIM + c * 8);
            float4 a = gw[0];
            float4 b = gw[1];
            float ws[8] = {a.x, a.y, a.z, a.w, b.x, b.y, b.z, b.w};
            float hv[8], lv[8];
            #pragma unroll
            for (int j = 0; j < 8; ++j) {
                __nv_bfloat16 h = __float2bfloat16_rn(ws[j]);
                hv[j] = __bfloat162float(h);
                lv[j] = ws[j] - hv[j];
            }
            uint4 H, Lo;
            H.x  = pack_bf16x2(hv[0], hv[1]); H.y  = pack_bf16x2(hv[2], hv[3]);
            H.z  = pack_bf16x2(hv[4], hv[5]); H.w  = pack_bf16x2(hv[6], hv[7]);
            Lo.x = pack_bf16x2(lv[0], lv[1]); Lo.y = pack_bf16x2(lv[2], lv[3]);
            Lo.z = pack_bf16x2(lv[4], lv[5]); Lo.w = pack_bf16x2(lv[6], lv[7]);
            int off = k * 128 + ((c ^ (k & 7)) << 4);
            *reinterpret_cast<uint4*>(smem + SM_B_HI + off) = H;
            *reinterpret_cast<uint4*>(smem + SM_B_LO + off) = Lo;
        }
        if (tid < H_DIM) { b1s[tid] = B1[tid]; W2s[tid] = W2[tid]; }
    }
    __syncthreads();

    // ---- GEMM1: per warp 32 edges x 64 h, K=128, 3 bf16 terms ----
    float acc[2][8][4];
    #pragma unroll
    for (int mt = 0; mt < 2; ++mt)
        #pragma unroll
        for (int nt = 0; nt < 8; ++nt)
            #pragma unroll
            for (int i = 0; i < 4; ++i) acc[mt][nt][i] = 0.0f;

    const uint32_t bRow = sbase + SM_B_HI + (L & 15) * 128;
    const uint32_t lsel = L >> 4;
    const uint32_t l7   = L & 7;

    #pragma unroll
    for (int kt = 0; kt < 8; ++kt) {
        // convert current prefetch buffer into A fragments (hi/lo)
        uint32_t ah0[4], ah1[4], al0[4], al1[4];
        {
            float2* cur = pf[kt & 1];
            // mt=0: rows g, g+8  -> cur[0..3]; mt=1: rows g+16, g+24 -> cur[4..7]
            cvt_split(cur[0], ah0[0], al0[0]);   // row g,    cols c0
            cvt_split(cur[2], ah0[1], al0[1]);   // row g+8,  cols c0
            cvt_split(cur[1], ah0[2], al0[2]);   // row g,    cols c0+8
            cvt_split(cur[3], ah0[3], al0[3]);   // row g+8,  cols c0+8
            cvt_split(cur[4], ah1[0], al1[0]);
            cvt_split(cur[6], ah1[1], al1[1]);
            cvt_split(cur[5], ah1[2], al1[2]);
            cvt_split(cur[7], ah1[3], al1[3]);
        }
        // prefetch kt+2
        if (kt < 6) {
            const float* kp = xp + (kt + 2) * 16;
            #pragma unroll
            for (int rr = 0; rr < 4; ++rr) {
                const float* rp = kp + rr * 8 * F_DIM;
                pf[kt & 1][rr * 2 + 0] = *reinterpret_cast<const float2*>(rp);
                pf[kt & 1][rr * 2 + 1] = *reinterpret_cast<const float2*>(rp + 8);
            }
        }

        const uint32_t bbase = bRow + kt * 2048;
        #pragma unroll
        for (int p = 0; p < 4; ++p) {
            // x4.trans: lanes 0-15 -> n-chunk 2p (k rows 0-7, 8-15),
            //           lanes 16-31 -> n-chunk 2p+1
            const uint32_t baddr = bbase + (((2 * p + lsel) ^ l7) << 4);
            uint32_t bh[4], bl[4];
            ldmx4t(baddr, bh);
            ldmx4t(baddr + 16384, bl);

            mma16816(acc[0][2 * p],     ah0, bh);
            mma16816(acc[1][2 * p],     ah1, bh);
            mma16816(acc[0][2 * p + 1], ah0, bh + 2);
            mma16816(acc[1][2 * p + 1], ah1, bh + 2);

            mma16816(acc[0][2 * p],     ah0, bl);
            mma16816(acc[1][2 * p],     ah1, bl);
            mma16816(acc[0][2 * p + 1], ah0, bl + 2);
            mma16816(acc[1][2 * p + 1], ah1, bl + 2);

            mma16816(acc[0][2 * p],     al0, bh);
            mma16816(acc[1][2 * p],     al1, bh);
            mma16816(acc[0][2 * p + 1], al0, bh + 2);
            mma16816(acc[1][2 * p + 1], al1, bh + 2);
        }
    }

    // ---- epilogue: bias + ssp + dot(W2); quad reduce over n ----
    {
        const float b2v = B2[0];
        #pragma unroll
        for (int mt = 0; mt < 2; ++mt) {
            #pragma unroll
            for (int half = 0; half < 2; ++half) {
                float s = 0.0f;
                #pragma unroll
                for (int nt = 0; nt < 8; ++nt) {
                    int h0 = nt * 8 + (L & 3) * 2;
                    float v0 = acc[mt][nt][half * 2 + 0];
                    float v1 = acc[mt][nt][half * 2 + 1];
                    s += ssp(v0 + b1s[h0])     * W2s[h0];
                    s += ssp(v1 + b1s[h0 + 1]) * W2s[h0 + 1];
                }
                s += __shfl_xor_sync(0xffffffffu, s, 1);
                s += __shfl_xor_sync(0xffffffffu, s, 2);
                if ((L & 3) == 0)
                    fms[m0 + mt * 16 + half * 8 + (L >> 2)] = s + b2v;
            }
        }
    }
    __syncthreads();

    // ---- per-edge force vector + 64-neighbor reduction ----
    {
        float fm = fms[tid];
        const float* up = U + ((size_t)g * TILE_E + tid) * 3;
        float v0 = fm * up[0];
        float v1 = fm * up[1];
        float v2 = fm * up[2];
        #pragma unroll
        for (int off = 16; off > 0; off >>= 1) {
            v0 += __shfl_down_sync(0xffffffffu, v0, off);
            v1 += __shfl_down_sync(0xffffffffu, v1, off);
            v2 += __shfl_down_sync(0xffffffffu, v2, off);
        }
        if (L == 0) {
            int atom = tid >> 6;
            atomicAdd(&acc6[atom * 3 + 0], v0);
            atomicAdd(&acc6[atom * 3 + 1], v1);
            atomicAdd(&acc6[atom * 3 + 2], v2);
        }
    }
    __syncthreads();

    if (tid < 6) out[(size_t)g * 6 + tid] = acc6[tid];
}

extern "C" void kernel_launch(void* const* d_in, const int* in_sizes, int n_in,
                              void* d_out, int out_size) {
    const float* X  = (const float*)d_in[0];
    const float* U  = (const float*)d_in[1];
    const float* W1 = (const float*)d_in[2];
    const float* B1 = (const float*)d_in[3];
    const float* W2 = (const float*)d_in[4];
    const float* B2 = (const float*)d_in[5];
    float* out = (float*)d_out;

    const int edges  = in_sizes[1] / 3;     // 524288
    const int blocks = edges / TILE_E;      // 4096

    cudaFuncSetAttribute(force_mapping_kernel,
                         cudaFuncAttributeMaxDynamicSharedMemorySize, SM_TOTAL);

    force_mapping_kernel<<<blocks, THREADS, SM_TOTAL>>>(X, U, W1, B1, W2, B2, out);
}

// round 14
// speedup vs baseline: 1.0004x; 1.0004x over previous
#include <cuda_runtime.h>
#include <cuda_bf16.h>
#include <cstdint>

#define F_DIM 128
#define H_DIM 64
#define TILE_E 128
#define THREADS 128

// ---- dynamic smem byte offsets ----
#define SM_B_HI 0            // 128 k-rows x 128 B (bf16 W hi), XOR-swizzled
#define SM_B_LO 16384
#define SM_B1   32768        // 64 f
#define SM_W2   33024        // 64 f
#define SM_FMS  33280        // 128 f
#define SM_ACC  33792        // 8 f
#define SM_TOTAL 33856

__device__ __forceinline__ uint32_t smem_u32(const void* p) {
    uint32_t a;
    asm("{ .reg .u64 t; cvta.to.shared.u64 t, %1; cvt.u32.u64 %0, t; }" : "=r"(a) : "l"(p));
    return a;
}
__device__ __forceinline__ uint32_t pack_bf16x2(float lo, float hi) {
    uint32_t r;
    asm("cvt.rn.bf16x2.f32 %0, %1, %2;" : "=r"(r) : "f"(hi), "f"(lo));
    return r;
}
// split one float2 into packed bf16x2 hi and lo parts
__device__ __forceinline__ void cvt_split(float2 v, uint32_t& h, uint32_t& l) {
    __nv_bfloat16 hx = __float2bfloat16_rn(v.x);
    __nv_bfloat16 hy = __float2bfloat16_rn(v.y);
    float fhx = __bfloat162float(hx);
    float fhy = __bfloat162float(hy);
    h = pack_bf16x2(fhx, fhy);
    l = pack_bf16x2(v.x - fhx, v.y - fhy);
}
__device__ __forceinline__ void ldmx4t(uint32_t addr, uint32_t* r) {
    asm volatile("ldmatrix.sync.aligned.m8n8.x4.trans.shared.b16 {%0,%1,%2,%3}, [%4];"
                 : "=r"(r[0]), "=r"(r[1]), "=r"(r[2]), "=r"(r[3]) : "r"(addr));
}
__device__ __forceinline__ void mma16816(float* c, const uint32_t* a, const uint32_t* b) {
    asm volatile(
        "mma.sync.aligned.m16n8k16.row.col.f32.bf16.bf16.f32 "
        "{%0,%1,%2,%3}, {%4,%5,%6,%7}, {%8,%9}, {%0,%1,%2,%3};"
        : "+f"(c[0]), "+f"(c[1]), "+f"(c[2]), "+f"(c[3])
        : "r"(a[0]), "r"(a[1]), "r"(a[2]), "r"(a[3]), "r"(b[0]), "r"(b[1]));
}
// shifted softplus: softplus(x) - ln(2)
__device__ __forceinline__ float ssp(float x) {
    float ax = fabsf(x);
    float l = __logf(1.0f + __expf(-ax));
    return fmaxf(x, 0.0f) + l - 0.69314718055994530942f;
}

__global__ __launch_bounds__(THREADS, 3)
void force_mapping_kernel(const float* __restrict__ X,
                          const float* __restrict__ U,
                          const float* __restrict__ W1,
                          const float* __restrict__ B1,
                          const float* __restrict__ W2,
                          const float* __restrict__ B2,
                          float* __restrict__ out)
{
    extern __shared__ char smem[];
    const uint32_t sbase = smem_u32(smem);
    const int tid = threadIdx.x;
    const int wid = tid >> 5;
    const int L   = tid & 31;
    const int g   = blockIdx.x;
    const int m0  = wid * 32;

    float* b1s  = reinterpret_cast<float*>(smem + SM_B1);
    float* W2s  = reinterpret_cast<float*>(smem + SM_W2);
    float* fms  = reinterpret_cast<float*>(smem + SM_FMS);
    float* acc6 = reinterpret_cast<float*>(smem + SM_ACC);

    if (tid < 8) acc6[tid] = 0.0f;

    // ---- A fragment base pointer: row = m0 + L/4, col = (L%4)*2 ----
    const float* xp = X + ((size_t)g * TILE_E + m0 + (L >> 2)) * F_DIM + (L & 3) * 2;

    // pf[buf][j]: j = row{0,8,16,24} x col{+0,+8}, interleaved (r0c0,r0c8,r1c0,...)
    float2 pf[2][8];
    #pragma unroll
    for (int rr = 0; rr < 4; ++rr) {
        const float* rp = xp + rr * 8 * F_DIM;
        pf[0][rr * 2 + 0] = *reinterpret_cast<const float2*>(rp);
        pf[0][rr * 2 + 1] = *reinterpret_cast<const float2*>(rp + 8);
        pf[1][rr * 2 + 0] = *reinterpret_cast<const float2*>(rp + 16);
        pf[1][rr * 2 + 1] = *reinterpret_cast<const float2*>(rp + 24);
    }

    // ---- convert W1 (K=128 rows x N=64, row-major) -> bf16 hi/lo smem, swizzled ----
    {
        #pragma unroll
        for (int it = 0; it < 8; ++it) {
            int q  = tid + THREADS * it;         // 0..1023
            int k  = q >> 3;                     // 0..127
            int c  = q & 7;                      // n chunk (8 floats)
            const float4* gw = reinterpret_cast<const float4*>(W1 + k * H_DIM + c * 8);
            float4 a = gw[0];
            float4 b = gw[1];
            float ws[8] = {a.x, a.y, a.z, a.w, b.x, b.y, b.z, b.w};
            float hv[8], lv[8];
            #pragma unroll
            for (int j = 0; j < 8; ++j) {
                __nv_bfloat16 h = __float2bfloat16_rn(ws[j]);
                hv[j] = __bfloat162float(h);
                lv[j] = ws[j] - hv[j];
            }
            uint4 H, Lo;
            H.x  = pack_bf16x2(hv[0], hv[1]); H.y  = pack_bf16x2(hv[2], hv[3]);
            H.z  = pack_bf16x2(hv[4], hv[5]); H.w  = pack_bf16x2(hv[6], hv[7]);
            Lo.x = pack_bf16x2(lv[0], lv[1]); Lo.y = pack_bf16x2(lv[2], lv[3]);
            Lo.z = pack_bf16x2(lv[4], lv[5]); Lo.w = pack_bf16x2(lv[6], lv[7]);
            int off = k * 128 + ((c ^ (k & 7)) << 4);
            *reinterpret_cast<uint4*>(smem + SM_B_HI + off) = H;
            *reinterpret_cast<uint4*>(smem + SM_B_LO + off) = Lo;
        }
        if (tid < H_DIM) { b1s[tid] = B1[tid]; W2s[tid] = W2[tid]; }
    }
    __syncthreads();

    // ---- GEMM1: per warp 32 edges x 64 h, K=128, 3 bf16 terms ----
    float acc[2][8][4];
    #pragma unroll
    for (int mt = 0; mt < 2; ++mt)
        #pragma unroll
        for (int nt = 0; nt < 8; ++nt)
            #pragma unroll
            for (int i = 0; i < 4; ++i) acc[mt][nt][i] = 0.0f;

    const uint32_t bRow = sbase + SM_B_HI + (L & 15) * 128;
    const uint32_t lsel = L >> 4;
    const uint32_t l7   = L & 7;

    #pragma unroll
    for (int kt = 0; kt < 8; ++kt) {
        // convert current prefetch buffer into A fragments (hi/lo)
        uint32_t ah0[4], ah1[4], al0[4], al1[4];
        {
            float2* cur = pf[kt & 1];
            // mt=0: rows g, g+8  -> cur[0..3]; mt=1: rows g+16, g+24 -> cur[4..7]
            cvt_split(cur[0], ah0[0], al0[0]);   // row g,    cols c0
            cvt_split(cur[2], ah0[1], al0[1]);   // row g+8,  cols c0
            cvt_split(cur[1], ah0[2], al0[2]);   // row g,    cols c0+8
            cvt_split(cur[3], ah0[3], al0[3]);   // row g+8,  cols c0+8
            cvt_split(cur[4], ah1[0], al1[0]);
            cvt_split(cur[6], ah1[1], al1[1]);
            cvt_split(cur[5], ah1[2], al1[2]);
            cvt_split(cur[7], ah1[3], al1[3]);
        }
        // prefetch kt+2
        if (kt < 6) {
            const float* kp = xp + (kt + 2) * 16;
            #pragma unroll
            for (int rr = 0; rr < 4; ++rr) {
                const float* rp = kp + rr * 8 * F_DIM;
                pf[kt & 1][rr * 2 + 0] = *reinterpret_cast<const float2*>(rp);
                pf[kt & 1][rr * 2 + 1] = *reinterpret_cast<const float2*>(rp + 8);
            }
        }

        const uint32_t bbase = bRow + kt * 2048;
        #pragma unroll
        for (int p = 0; p < 4; ++p) {
            // x4.trans: lanes 0-15 -> n-chunk 2p (k rows 0-7, 8-15),
            //           lanes 16-31 -> n-chunk 2p+1
            const uint32_t baddr = bbase + (((2 * p + lsel) ^ l7) << 4);
            uint32_t bh[4], bl[4];
            ldmx4t(baddr, bh);
            ldmx4t(baddr + 16384, bl);

            mma16816(acc[0][2 * p],     ah0, bh);
            mma16816(acc[1][2 * p],     ah1, bh);
            mma16816(acc[0][2 * p + 1], ah0, bh + 2);
            mma16816(acc[1][2 * p + 1], ah1, bh + 2);

            mma16816(acc[0][2 * p],     ah0, bl);
            mma16816(acc[1][2 * p],     ah1, bl);
            mma16816(acc[0][2 * p + 1], ah0, bl + 2);
            mma16816(acc[1][2 * p + 1], ah1, bl + 2);

            mma16816(acc[0][2 * p],     al0, bh);
            mma16816(acc[1][2 * p],     al1, bh);
            mma16816(acc[0][2 * p + 1], al0, bh + 2);
            mma16816(acc[1][2 * p + 1], al1, bh + 2);
        }
    }

    // ---- epilogue: bias + ssp + dot(W2); quad reduce over n ----
    {
        const float b2v = B2[0];
        #pragma unroll
        for (int mt = 0; mt < 2; ++mt) {
            #pragma unroll
            for (int half = 0; half < 2; ++half) {
                float s = 0.0f;
                #pragma unroll
                for (int nt = 0; nt < 8; ++nt) {
                    int h0 = nt * 8 + (L & 3) * 2;
                    float v0 = acc[mt][nt][half * 2 + 0];
                    float v1 = acc[mt][nt][half * 2 + 1];
                    s += ssp(v0 + b1s[h0])     * W2s[h0];
                    s += ssp(v1 + b1s[h0 + 1]) * W2s[h0 + 1];
                }
                s += __shfl_xor_sync(0xffffffffu, s, 1);
                s += __shfl_xor_sync(0xffffffffu, s, 2);
                if ((L & 3) == 0)
                    fms[m0 + mt * 16 + half * 8 + (L >> 2)] = s + b2v;
            }
        }
    }
    __syncthreads();

    // ---- per-edge force vector + 64-neighbor reduction ----
    {
        float fm = fms[tid];
        const float* up = U + ((size_t)g * TILE_E + tid) * 3;
        float v0 = fm * up[0];
        float v1 = fm * up[1];
        float v2 = fm * up[2];
        #pragma unroll
        for (int off = 16; off > 0; off >>= 1) {
            v0 += __shfl_down_sync(0xffffffffu, v0, off);
            v1 += __shfl_down_sync(0xffffffffu, v1, off);
            v2 += __shfl_down_sync(0xffffffffu, v2, off);
        }
        if (L == 0) {
            int atom = tid >> 6;
            atomicAdd(&acc6[atom * 3 + 0], v0);
            atomicAdd(&acc6[atom * 3 + 1], v1);
            atomicAdd(&acc6[atom * 3 + 2], v2);
        }
    }
    __syncthreads();

    if (tid < 6) out[(size_t)g * 6 + tid] = acc6[tid];
}

extern "C" void kernel_launch(void* const* d_in, const int* in_sizes, int n_in,
                              void* d_out, int out_size) {
    const float* X  = (const float*)d_in[0];
    const float* U  = (const float*)d_in[1];
    const float* W1 = (const float*)d_in[2];
    const float* B1 = (const float*)d_in[3];
    const float* W2 = (const float*)d_in[4];
    const float* B2 = (const float*)d_in[5];
    float* out = (float*)d_out;

    const int edges  = in_sizes[1] / 3;     // 524288
    const int blocks = edges / TILE_E;      // 4096

    cudaFuncSetAttribute(force_mapping_kernel,
                         cudaFuncAttributeMaxDynamicSharedMemorySize, SM_TOTAL);

    force_mapping_kernel<<<blocks, THREADS, SM_TOTAL>>>(X, U, W1, B1, W2, B2, out);
}